// round 10
// baseline (speedup 1.0000x reference)
#include <cuda_runtime.h>
#include <cstdint>

// out[b,t,c] = sum_s exp(-4*(sw[b,t] + s - t)^2) * input[b,s,c]
// WIDTH=0.25 -> 3-tap window {r-1, r, r+1}, r = round(t - sw); dropped taps
// weigh <= exp(-9) = 1.23e-4 vs kept sum >= 0.74 -> rel err ~3e-4 worst case
// (threshold 1e-3; measured 4.5e-5). 2-tap rejected: ~4e-3 > threshold.
//
// Round-10: minimum-T_CTA / minimum-load-burst configuration per the B300
// cross-CTA L1tex-queue spread model (ncu durations anti-correlate with
// occupancy across rounds -> queue contention, not parallelism, limits):
//  - 2 t per warp, SINGLE phase: 6 LDG.128 front batch (minimum possible),
//    one load-latency-deep critical path
//  - 256-thr CTAs, grid (128,16)=2048: fine scheduling granularity
//  - lean math: exp2 factorization (3 ALU + 3 EX2 per t), base-pointer +
//    immediate-offset tap addressing, float2 sw broadcast
//  - streaming stores (st.global.cs, evict-first) so 16.8MB of output
//    writes don't evict the L2-resident input between graph replays

#define S_DIM 4096
#define T_DIM 2048
#define C_DIM 128
#define C4    (C_DIM / 4)

__device__ __forceinline__ float ex2(float x) {
    float y;
    asm("ex2.approx.f32 %0, %1;" : "=f"(y) : "f"(x));
    return y;
}

__device__ __forceinline__ void st_cs_v4(float4* p, float4 v) {
    asm volatile("st.global.cs.v4.f32 [%0], {%1, %2, %3, %4};"
                 :: "l"(p), "f"(v.x), "f"(v.y), "f"(v.z), "f"(v.w));
}

__global__ __launch_bounds__(256)
void shifting_window_kernel(const float* __restrict__ inp,
                            const float* __restrict__ sw,
                            float* __restrict__ out) {
    const int b    = blockIdx.y;
    const int warp = threadIdx.x >> 5;                 // 0..7
    const int lane = threadIdx.x & 31;
    const int t0   = (blockIdx.x << 4) + (warp << 1);  // 2 t per warp

    const float4* __restrict__ row =
        (const float4*)(inp + (size_t)b * S_DIM * C_DIM);

    // sw[t0], sw[t0+1] in one broadcast float2 (t0 % 2 == 0, 8B aligned).
    const float2 swv = *(const float2*)(sw + b * T_DIM + t0);
    const float wv[2] = {swv.x, swv.y};

    int   r[2];
    float wm[2], w0[2], wp[2];
#pragma unroll
    for (int j = 0; j < 2; ++j) {
        r[j] = __float2int_rn((float)(t0 + j) - wv[j]);
        const float f = wv[j] + (float)(r[j] - (t0 + j));   // frac in [-0.5,0.5]
        const float A = -5.770780f * f * f;                 // -4 f^2 log2(e)
        const float u = 11.541560f * f;                     //  8 f   log2(e)
        w0[j] = ex2(A);
        wm[j] = ex2(A + u - 5.770780f);                     // tap r-1
        wp[j] = ex2(A - u - 5.770780f);                     // tap r+1
    }

    if (t0 >= 8) {
        // Hot path: s in [t-6, t+6] subset of [2, 2054) -> no bounds checks.
        float4 acc[2];
#pragma unroll
        for (int j = 0; j < 2; ++j) {
            // Base pointer at tap r-1; taps at +0 / +512B / +1024B.
            const float4* p = &row[(r[j] - 1) * C4 + lane];
            const float4 vm = p[0];
            const float4 v0 = p[C4];
            const float4 vp = p[2 * C4];
            float4 a;
            a.x = wm[j] * vm.x; a.y = wm[j] * vm.y;
            a.z = wm[j] * vm.z; a.w = wm[j] * vm.w;
            a.x = fmaf(w0[j], v0.x, a.x); a.y = fmaf(w0[j], v0.y, a.y);
            a.z = fmaf(w0[j], v0.z, a.z); a.w = fmaf(w0[j], v0.w, a.w);
            a.x = fmaf(wp[j], vp.x, a.x); a.y = fmaf(wp[j], vp.y, a.y);
            a.z = fmaf(wp[j], vp.z, a.z); a.w = fmaf(wp[j], vp.w, a.w);
            acc[j] = a;
        }
#pragma unroll
        for (int j = 0; j < 2; ++j) {
            float4* o = (float4*)(out + ((size_t)b * T_DIM + (t0 + j)) * C_DIM);
            st_cs_v4(o + lane, acc[j]);
        }
    } else {
        // Cold path (4 warps in the whole grid): clamp address, zero weight.
#pragma unroll
        for (int j = 0; j < 2; ++j) {
            float4 acc = make_float4(0.f, 0.f, 0.f, 0.f);
            const float w3[3] = {wm[j], w0[j], wp[j]};
#pragma unroll
            for (int i = -1; i <= 1; ++i) {
                const int s    = r[j] + i;
                float     wgt  = w3[i + 1];
                if (s < 0) wgt = 0.f;
                const int s_ld = (s < 0) ? 0 : s;
                const float4 v = row[s_ld * C4 + lane];
                acc.x = fmaf(wgt, v.x, acc.x);
                acc.y = fmaf(wgt, v.y, acc.y);
                acc.z = fmaf(wgt, v.z, acc.z);
                acc.w = fmaf(wgt, v.w, acc.w);
            }
            float4* o = (float4*)(out + ((size_t)b * T_DIM + (t0 + j)) * C_DIM);
            st_cs_v4(o + lane, acc);
        }
    }
}

extern "C" void kernel_launch(void* const* d_in, const int* in_sizes, int n_in,
                              void* d_out, int out_size) {
    const float* inp = (const float*)d_in[0];   // (B, S, C) fp32
    const float* sw  = (const float*)d_in[1];   // (B, T)   fp32
    float* out       = (float*)d_out;           // (B, T, C) fp32

    dim3 grid(T_DIM / 16, 16, 1);   // 16 t per block -> (128, 16) = 2048 blocks
    dim3 block(256, 1, 1);
    shifting_window_kernel<<<grid, block>>>(inp, sw, out);
}